// round 1
// baseline (speedup 1.0000x reference)
#include <cuda_runtime.h>
#include <cuda_bf16.h>

// SimSiam loss, algebraically reduced:
//   loss = -0.5 * sum_c( P_c . Z_c  -  sum_{i in c} pn_i.zn_i ) / npairs
// where P_c/Z_c are per-class sums of L2-normalized rows and
// npairs = sum_c m_c*(m_c-1)/2.
// This avoids the 8192x8192 similarity GEMM entirely: O(n*d) work.

#define NCLASS 512
#define D      128
#define EPS    1e-8f

// Scratch (no cudaMalloc allowed): class accumulators + scalars.
__device__ float  g_P[NCLASS * D];
__device__ float  g_Z[NCLASS * D];
__device__ int    g_cnt[NCLASS];
__device__ double g_Ddiag;    // sum_i pn_i . zn_i
__device__ int    g_is64;     // 1 if targets buffer is int64, 0 if int32

// ---------------------------------------------------------------------------
__global__ void zero_kernel() {
    int i = blockIdx.x * blockDim.x + threadIdx.x;
    if (i < NCLASS * D) { g_P[i] = 0.0f; g_Z[i] = 0.0f; }
    if (i < NCLASS)     g_cnt[i] = 0;
    if (i == 0)         g_Ddiag = 0.0;
}

// Detect whether the targets buffer holds int64 or int32 labels.
// Read only n/2 int64 slots (never overruns an int32 buffer of n elements).
// If the buffer is really int32, the int64 view packs two labels per slot and
// is >= NCLASS with overwhelming probability for any nonzero odd-index label.
__global__ void detect_kernel(const long long* __restrict__ t, int n_half) {
    __shared__ int bad;
    if (threadIdx.x == 0) bad = 0;
    __syncthreads();
    for (int i = threadIdx.x; i < n_half; i += blockDim.x) {
        long long v = t[i];
        if (v < 0 || v >= NCLASS) bad = 1;
    }
    __syncthreads();
    if (threadIdx.x == 0) g_is64 = bad ? 0 : 1;
}

// ---------------------------------------------------------------------------
// One warp per row: load 128 floats of ps and zs as float4 (1 per lane),
// warp-reduce norms + dot, scatter normalized rows into per-class sums.
__global__ void accum_kernel(const float* __restrict__ ps,
                             const float* __restrict__ zs,
                             const void*  __restrict__ tgv,
                             int n_rows) {
    int warp = (blockIdx.x * blockDim.x + threadIdx.x) >> 5;
    int lane = threadIdx.x & 31;
    if (warp >= n_rows) return;

    float4 a = reinterpret_cast<const float4*>(ps)[warp * (D / 4) + lane];
    float4 b = reinterpret_cast<const float4*>(zs)[warp * (D / 4) + lane];

    float sa = a.x * a.x + a.y * a.y + a.z * a.z + a.w * a.w;
    float sb = b.x * b.x + b.y * b.y + b.z * b.z + b.w * b.w;
    float dp = a.x * b.x + a.y * b.y + a.z * b.z + a.w * b.w;

    #pragma unroll
    for (int o = 16; o > 0; o >>= 1) {
        sa += __shfl_xor_sync(0xFFFFFFFFu, sa, o);
        sb += __shfl_xor_sync(0xFFFFFFFFu, sb, o);
        dp += __shfl_xor_sync(0xFFFFFFFFu, dp, o);
    }

    float invp = 1.0f / fmaxf(sqrtf(sa), EPS);
    float invz = 1.0f / fmaxf(sqrtf(sb), EPS);

    int t;
    if (g_is64) t = (int)reinterpret_cast<const long long*>(tgv)[warp];
    else        t = reinterpret_cast<const int*>(tgv)[warp];

    float* P = &g_P[t * D + lane * 4];
    float* Z = &g_Z[t * D + lane * 4];
    atomicAdd(P + 0, a.x * invp);
    atomicAdd(P + 1, a.y * invp);
    atomicAdd(P + 2, a.z * invp);
    atomicAdd(P + 3, a.w * invp);
    atomicAdd(Z + 0, b.x * invz);
    atomicAdd(Z + 1, b.y * invz);
    atomicAdd(Z + 2, b.z * invz);
    atomicAdd(Z + 3, b.w * invz);

    if (lane == 0) {
        atomicAdd(&g_cnt[t], 1);
        atomicAdd(&g_Ddiag, (double)(dp * invp * invz));
    }
}

// ---------------------------------------------------------------------------
__global__ void finalize_kernel(float* __restrict__ out) {
    __shared__ double    sdot[128];
    __shared__ long long spair[128];
    int tid = threadIdx.x;

    double    acc   = 0.0;
    long long pairs = 0;
    for (int c = tid; c < NCLASS; c += 128) {
        const float* P = &g_P[c * D];
        const float* Z = &g_Z[c * D];
        double d = 0.0;
        #pragma unroll 8
        for (int k = 0; k < D; k++) d += (double)P[k] * (double)Z[k];
        acc += d;
        long long m = (long long)g_cnt[c];
        pairs += m * (m - 1) / 2;
    }
    sdot[tid]  = acc;
    spair[tid] = pairs;
    __syncthreads();
    for (int s = 64; s > 0; s >>= 1) {
        if (tid < s) { sdot[tid] += sdot[tid + s]; spair[tid] += spair[tid + s]; }
        __syncthreads();
    }
    if (tid == 0) {
        double S  = sdot[0] - g_Ddiag;
        double np = (spair[0] > 0) ? (double)spair[0] : 1.0;
        out[0] = (float)(-0.5 * S / np);
    }
}

// ---------------------------------------------------------------------------
extern "C" void kernel_launch(void* const* d_in, const int* in_sizes, int n_in,
                              void* d_out, int out_size) {
    const float* ps  = (const float*)d_in[0];
    const float* zs  = (const float*)d_in[1];
    const void*  tgt = d_in[2];
    float*       out = (float*)d_out;

    int n_rows = in_sizes[0] / D;   // 8192

    // zero scratch
    int zn = NCLASS * D;
    zero_kernel<<<(zn + 255) / 256, 256>>>();

    // sniff targets dtype (int32 vs int64), reading at most n_rows/2 int64 slots
    detect_kernel<<<1, 256>>>((const long long*)tgt, n_rows / 2);

    // main accumulation: 1 warp/row, 8 warps/block
    int blocks = (n_rows + 7) / 8;
    accum_kernel<<<blocks, 256>>>(ps, zs, tgt, n_rows);

    // finalize
    finalize_kernel<<<1, 128>>>(out);
}

// round 2
// speedup vs baseline: 4.5701x; 4.5701x over previous
#include <cuda_runtime.h>
#include <cuda_bf16.h>

// SimSiam loss, algebraically reduced:
//   loss = -0.5 * sum_c( P_c . Z_c  -  sum_{i in c} pn_i.zn_i ) / npairs
// where P_c/Z_c are per-class sums of L2-normalized rows and
// npairs = sum_c m_c*(m_c-1)/2.   O(n*d) work, no 8192x8192 GEMM.

#define NCLASS 512
#define D      128
#define EPS    1e-8f

// Scratch (no cudaMalloc allowed): class accumulators + scalars.
__device__ float              g_P[NCLASS * D];
__device__ float              g_Z[NCLASS * D];
__device__ int                g_cnt[NCLASS];
__device__ double             g_Ddiag;   // sum_i pn_i . zn_i
__device__ double             g_S;       // sum_c P_c . Z_c
__device__ unsigned long long g_pairs;   // sum_c m(m-1)/2
__device__ int                g_is64;    // targets dtype flag

// ---------------------------------------------------------------------------
__global__ void zero_kernel() {
    int i = blockIdx.x * blockDim.x + threadIdx.x;
    // vectorized zero of g_P/g_Z (NCLASS*D = 65536 floats each = 16384 float4)
    if (i < NCLASS * D / 4) {
        reinterpret_cast<float4*>(g_P)[i] = make_float4(0.f, 0.f, 0.f, 0.f);
        reinterpret_cast<float4*>(g_Z)[i] = make_float4(0.f, 0.f, 0.f, 0.f);
    }
    if (i < NCLASS) g_cnt[i] = 0;
    if (i == 0) { g_Ddiag = 0.0; g_S = 0.0; g_pairs = 0ull; }
}

// Detect whether the targets buffer holds int64 or int32 labels.
// Reads only n/2 int64 slots (never overruns an int32 buffer of n elements).
__global__ void detect_kernel(const long long* __restrict__ t, int n_half) {
    __shared__ int bad;
    if (threadIdx.x == 0) bad = 0;
    __syncthreads();
    for (int i = threadIdx.x; i < n_half; i += blockDim.x) {
        long long v = t[i];
        if (v < 0 || v >= NCLASS) bad = 1;
    }
    __syncthreads();
    if (threadIdx.x == 0) g_is64 = bad ? 0 : 1;
}

// ---------------------------------------------------------------------------
// One warp per row: load 128 floats of ps and zs as float4 (1 per lane),
// warp-reduce norms + dot, scatter normalized rows into per-class sums.
// Diag contributions are block-reduced -> ONE double atomic per block.
__global__ void accum_kernel(const float* __restrict__ ps,
                             const float* __restrict__ zs,
                             const void*  __restrict__ tgv,
                             int n_rows) {
    __shared__ double sdp[8];   // one slot per warp (256 threads = 8 warps)
    int warp_in_blk = threadIdx.x >> 5;
    int lane        = threadIdx.x & 31;
    int warp        = (blockIdx.x * blockDim.x + threadIdx.x) >> 5;
    bool active     = (warp < n_rows);

    double diag = 0.0;
    if (active) {
        float4 a = reinterpret_cast<const float4*>(ps)[warp * (D / 4) + lane];
        float4 b = reinterpret_cast<const float4*>(zs)[warp * (D / 4) + lane];

        float sa = a.x * a.x + a.y * a.y + a.z * a.z + a.w * a.w;
        float sb = b.x * b.x + b.y * b.y + b.z * b.z + b.w * b.w;
        float dp = a.x * b.x + a.y * b.y + a.z * b.z + a.w * b.w;

        #pragma unroll
        for (int o = 16; o > 0; o >>= 1) {
            sa += __shfl_xor_sync(0xFFFFFFFFu, sa, o);
            sb += __shfl_xor_sync(0xFFFFFFFFu, sb, o);
            dp += __shfl_xor_sync(0xFFFFFFFFu, dp, o);
        }

        float invp = 1.0f / fmaxf(sqrtf(sa), EPS);
        float invz = 1.0f / fmaxf(sqrtf(sb), EPS);

        int t;
        if (g_is64) t = (int)reinterpret_cast<const long long*>(tgv)[warp];
        else        t = reinterpret_cast<const int*>(tgv)[warp];

        float* P = &g_P[t * D + lane * 4];
        float* Z = &g_Z[t * D + lane * 4];
        atomicAdd(P + 0, a.x * invp);
        atomicAdd(P + 1, a.y * invp);
        atomicAdd(P + 2, a.z * invp);
        atomicAdd(P + 3, a.w * invp);
        atomicAdd(Z + 0, b.x * invz);
        atomicAdd(Z + 1, b.y * invz);
        atomicAdd(Z + 2, b.z * invz);
        atomicAdd(Z + 3, b.w * invz);

        if (lane == 0) {
            atomicAdd(&g_cnt[t], 1);
            diag = (double)(dp * invp * invz);
        }
    }
    if (lane == 0) sdp[warp_in_blk] = diag;
    __syncthreads();
    if (threadIdx.x == 0) {
        double s = sdp[0] + sdp[1] + sdp[2] + sdp[3]
                 + sdp[4] + sdp[5] + sdp[6] + sdp[7];
        atomicAdd(&g_Ddiag, s);
    }
}

// ---------------------------------------------------------------------------
// One block per class: fp32 dot of P_c and Z_c, plus pair count.
__global__ void classdot_kernel() {
    __shared__ float w[4];
    int c    = blockIdx.x;
    int k    = threadIdx.x;          // 0..127
    int lane = k & 31;
    int wid  = k >> 5;

    float prod = g_P[c * D + k] * g_Z[c * D + k];
    #pragma unroll
    for (int o = 16; o > 0; o >>= 1)
        prod += __shfl_xor_sync(0xFFFFFFFFu, prod, o);
    if (lane == 0) w[wid] = prod;
    __syncthreads();
    if (k == 0) {
        double s = (double)w[0] + (double)w[1] + (double)w[2] + (double)w[3];
        atomicAdd(&g_S, s);
        unsigned long long m = (unsigned long long)g_cnt[c];
        atomicAdd(&g_pairs, m * (m - 1ull) / 2ull);
    }
}

// ---------------------------------------------------------------------------
__global__ void epilogue_kernel(float* __restrict__ out) {
    double np = (g_pairs > 0ull) ? (double)g_pairs : 1.0;
    out[0] = (float)(-0.5 * (g_S - g_Ddiag) / np);
}

// ---------------------------------------------------------------------------
extern "C" void kernel_launch(void* const* d_in, const int* in_sizes, int n_in,
                              void* d_out, int out_size) {
    const float* ps  = (const float*)d_in[0];
    const float* zs  = (const float*)d_in[1];
    const void*  tgt = d_in[2];
    float*       out = (float*)d_out;

    int n_rows = in_sizes[0] / D;   // 8192

    zero_kernel<<<(NCLASS * D / 4 + 255) / 256, 256>>>();
    detect_kernel<<<1, 256>>>((const long long*)tgt, n_rows / 2);
    accum_kernel<<<(n_rows + 7) / 8, 256>>>(ps, zs, tgt, n_rows);
    classdot_kernel<<<NCLASS, D>>>();
    epilogue_kernel<<<1, 1>>>(out);
}

// round 3
// speedup vs baseline: 6.7483x; 1.4766x over previous
#include <cuda_runtime.h>
#include <cuda_bf16.h>

// SimSiam loss, algebraically reduced:
//   loss = -0.5 * sum_c( P_c . Z_c  -  sum_{i in c} pn_i.zn_i ) / npairs
// where P_c/Z_c are per-class sums of L2-normalized rows and
// npairs = sum_c m_c*(m_c-1)/2.   O(n*d) work, no 8192x8192 GEMM.
//
// Scratch invariant: all __device__ scratch is ZERO at kernel_launch entry
// (zero-initialized at module load; the final kernel re-zeros everything it
// dirtied before finishing). So no separate zeroing pass is needed.

#define NCLASS 512
#define D      128
#define EPS    1e-8f

__device__ float              g_P[NCLASS * D];
__device__ float              g_Z[NCLASS * D];
__device__ int                g_cnt[NCLASS];
__device__ double             g_Ddiag;   // sum_i pn_i . zn_i
__device__ double             g_S;       // sum_c P_c . Z_c
__device__ unsigned long long g_pairs;   // sum_c m(m-1)/2
__device__ int                g_bad;     // !=0 -> targets are int32
__device__ unsigned int       g_done;    // last-block counter for final kernel

// 128-bit reduction into global memory (sm_90+), no return value.
__device__ __forceinline__ void red_add_v4(float* p, float x, float y, float z, float w) {
    asm volatile("red.global.add.v4.f32 [%0], {%1, %2, %3, %4};"
                 :: "l"(p), "f"(x), "f"(y), "f"(z), "f"(w) : "memory");
}

// ---------------------------------------------------------------------------
// Targets dtype sniff. View buffer as int64, read only n/2 slots (never
// overruns an int32 buffer of n elements). int64 labels in [0,512) pass;
// an int32 buffer packs two labels per slot -> some slot >= 2^32 w.h.p.
__global__ void detect_kernel(const long long* __restrict__ t, int n_half) {
    int i = blockIdx.x * blockDim.x + threadIdx.x;
    int stride = gridDim.x * blockDim.x;
    int bad = 0;
    for (; i < n_half; i += stride) {
        long long v = t[i];
        if (v < 0 || v >= NCLASS) bad = 1;
    }
    // warp-level OR then one atomic per warp at most
    bad = __any_sync(0xFFFFFFFFu, bad);
    if (bad && (threadIdx.x & 31) == 0) atomicOr(&g_bad, 1);
}

// ---------------------------------------------------------------------------
// One warp per row: float4 loads, warp-reduce norms + dot, scatter normalized
// rows into per-class sums with 128-bit vector atomics.
__global__ void accum_kernel(const float* __restrict__ ps,
                             const float* __restrict__ zs,
                             const void*  __restrict__ tgv,
                             int n_rows) {
    __shared__ double sdp[8];
    int warp_in_blk = threadIdx.x >> 5;
    int lane        = threadIdx.x & 31;
    int warp        = (blockIdx.x * blockDim.x + threadIdx.x) >> 5;

    double diag = 0.0;
    if (warp < n_rows) {
        float4 a = reinterpret_cast<const float4*>(ps)[warp * (D / 4) + lane];
        float4 b = reinterpret_cast<const float4*>(zs)[warp * (D / 4) + lane];

        float sa = a.x * a.x + a.y * a.y + a.z * a.z + a.w * a.w;
        float sb = b.x * b.x + b.y * b.y + b.z * b.z + b.w * b.w;
        float dp = a.x * b.x + a.y * b.y + a.z * b.z + a.w * b.w;

        #pragma unroll
        for (int o = 16; o > 0; o >>= 1) {
            sa += __shfl_xor_sync(0xFFFFFFFFu, sa, o);
            sb += __shfl_xor_sync(0xFFFFFFFFu, sb, o);
            dp += __shfl_xor_sync(0xFFFFFFFFu, dp, o);
        }

        float invp = 1.0f / fmaxf(sqrtf(sa), EPS);
        float invz = 1.0f / fmaxf(sqrtf(sb), EPS);

        int t;
        if (g_bad == 0) t = (int)reinterpret_cast<const long long*>(tgv)[warp];
        else            t = reinterpret_cast<const int*>(tgv)[warp];

        red_add_v4(&g_P[t * D + lane * 4], a.x * invp, a.y * invp, a.z * invp, a.w * invp);
        red_add_v4(&g_Z[t * D + lane * 4], b.x * invz, b.y * invz, b.z * invz, b.w * invz);

        if (lane == 0) {
            atomicAdd(&g_cnt[t], 1);
            diag = (double)(dp * invp * invz);
        }
    }
    if (lane == 0) sdp[warp_in_blk] = diag;
    __syncthreads();
    if (threadIdx.x == 0) {
        double s = sdp[0] + sdp[1] + sdp[2] + sdp[3]
                 + sdp[4] + sdp[5] + sdp[6] + sdp[7];
        atomicAdd(&g_Ddiag, s);
    }
}

// ---------------------------------------------------------------------------
// Fused: per-class dot (warp per class) + pair count + scratch re-zero +
// last-block epilogue. grid = NCLASS/8 blocks of 256 threads.
__global__ void final_kernel(float* __restrict__ out, int n_blocks) {
    int lane = threadIdx.x & 31;
    int wid  = threadIdx.x >> 5;                 // 0..7
    int c    = blockIdx.x * 8 + wid;             // class handled by this warp
    int idx  = c * (D / 4) + lane;               // float4 index into g_P/g_Z

    float4 p = reinterpret_cast<const float4*>(g_P)[idx];
    float4 z = reinterpret_cast<const float4*>(g_Z)[idx];
    float dot = p.x * z.x + p.y * z.y + p.z * z.z + p.w * z.w;
    #pragma unroll
    for (int o = 16; o > 0; o >>= 1)
        dot += __shfl_xor_sync(0xFFFFFFFFu, dot, o);

    if (lane == 0) {
        atomicAdd(&g_S, (double)dot);
        unsigned long long m = (unsigned long long)g_cnt[c];
        if (m > 1ull) atomicAdd(&g_pairs, m * (m - 1ull) / 2ull);
    }

    // Re-zero the slices this block owns (restores launch-entry invariant).
    float4 zero4 = make_float4(0.f, 0.f, 0.f, 0.f);
    reinterpret_cast<float4*>(g_P)[idx] = zero4;
    reinterpret_cast<float4*>(g_Z)[idx] = zero4;
    if (lane == 0) g_cnt[c] = 0;

    __syncthreads();
    __threadfence();
    if (threadIdx.x == 0) {
        unsigned int done = atomicAdd(&g_done, 1u);
        if (done == (unsigned int)(n_blocks - 1)) {
            // last block: epilogue + scalar reset
            double np = (g_pairs > 0ull) ? (double)g_pairs : 1.0;
            out[0] = (float)(-0.5 * (g_S - g_Ddiag) / np);
            g_S = 0.0; g_Ddiag = 0.0; g_pairs = 0ull;
            g_bad = 0; g_done = 0u;
        }
    }
}

// ---------------------------------------------------------------------------
extern "C" void kernel_launch(void* const* d_in, const int* in_sizes, int n_in,
                              void* d_out, int out_size) {
    const float* ps  = (const float*)d_in[0];
    const float* zs  = (const float*)d_in[1];
    const void*  tgt = d_in[2];
    float*       out = (float*)d_out;

    int n_rows = in_sizes[0] / D;   // 8192

    detect_kernel<<<8, 256>>>((const long long*)tgt, n_rows / 2);
    accum_kernel<<<(n_rows + 7) / 8, 256>>>(ps, zs, tgt, n_rows);
    int fb = NCLASS / 8;            // 64 blocks
    final_kernel<<<fb, 256>>>(out, fb);
}

// round 4
// speedup vs baseline: 7.8701x; 1.1662x over previous
#include <cuda_runtime.h>
#include <cuda_bf16.h>

// SimSiam loss, algebraically reduced:
//   loss = -0.5 * sum_c( P_c . Z_c  -  sum_{i in c} pn_i.zn_i ) / npairs
// where P_c/Z_c are per-class sums of L2-normalized rows and
// npairs = sum_c m_c*(m_c-1)/2.   O(n*d) work, no 8192x8192 GEMM.
//
// Scratch invariant: all __device__ scratch is ZERO at kernel_launch entry
// (zero-initialized at module load; final_kernel re-zeros everything it
// dirtied before finishing). So no separate zeroing pass is needed.
//
// Targets dtype (int64 vs int32) is sniffed IN-BLOCK: warp 0 of each accum
// block reads the first 64 int64-view slots (512 bytes — within bounds for
// either dtype at n=8192) and checks each is in [0, NCLASS). An int32 buffer
// viewed as int64 passes a slot only when the odd label is 0 AND even label
// < 512 (prob ~1/512 per slot); 64 slots make misdetection ~2^-576. All
// blocks compute the identical flag, so behavior stays deterministic.

#define NCLASS 512
#define D      128
#define EPS    1e-8f

__device__ float              g_P[NCLASS * D];
__device__ float              g_Z[NCLASS * D];
__device__ int                g_cnt[NCLASS];
__device__ double             g_Ddiag;   // sum_i pn_i . zn_i
__device__ double             g_S;       // sum_c P_c . Z_c
__device__ unsigned long long g_pairs;   // sum_c m(m-1)/2
__device__ unsigned int       g_done;    // last-block counter for final kernel

// 128-bit reduction into global memory (sm_90+), no return value.
__device__ __forceinline__ void red_add_v4(float* p, float x, float y, float z, float w) {
    asm volatile("red.global.add.v4.f32 [%0], {%1, %2, %3, %4};"
                 :: "l"(p), "f"(x), "f"(y), "f"(z), "f"(w) : "memory");
}

// ---------------------------------------------------------------------------
// One warp per row: float4 loads, warp-reduce norms + dot, scatter normalized
// rows into per-class sums with 128-bit vector atomics. In-block dtype sniff.
__global__ void accum_kernel(const float* __restrict__ ps,
                             const float* __restrict__ zs,
                             const void*  __restrict__ tgv,
                             int n_rows) {
    __shared__ double sdp[8];
    __shared__ int    s_is64;

    int warp_in_blk = threadIdx.x >> 5;
    int lane        = threadIdx.x & 31;
    int warp        = (blockIdx.x * blockDim.x + threadIdx.x) >> 5;

    // --- dtype sniff (warp 0): read int64-view slots [0, 64) ---
    if (warp_in_blk == 0) {
        const long long* t64 = (const long long*)tgv;
        int nslots = n_rows / 2;           // int64 slots that are safe either way
        int k = (nslots < 64) ? nslots : 64;
        int bad = 0;
        for (int i = lane; i < k; i += 32) {
            long long v = __ldg(&t64[i]);
            if (v < 0 || v >= NCLASS) bad = 1;
        }
        bad = __any_sync(0xFFFFFFFFu, bad);
        if (lane == 0) s_is64 = !bad;
    }
    __syncthreads();
    int is64 = s_is64;

    double diag = 0.0;
    if (warp < n_rows) {
        float4 a = reinterpret_cast<const float4*>(ps)[warp * (D / 4) + lane];
        float4 b = reinterpret_cast<const float4*>(zs)[warp * (D / 4) + lane];

        float sa = a.x * a.x + a.y * a.y + a.z * a.z + a.w * a.w;
        float sb = b.x * b.x + b.y * b.y + b.z * b.z + b.w * b.w;
        float dp = a.x * b.x + a.y * b.y + a.z * b.z + a.w * b.w;

        #pragma unroll
        for (int o = 16; o > 0; o >>= 1) {
            sa += __shfl_xor_sync(0xFFFFFFFFu, sa, o);
            sb += __shfl_xor_sync(0xFFFFFFFFu, sb, o);
            dp += __shfl_xor_sync(0xFFFFFFFFu, dp, o);
        }

        float invp = 1.0f / fmaxf(sqrtf(sa), EPS);
        float invz = 1.0f / fmaxf(sqrtf(sb), EPS);

        int t;
        if (is64) t = (int)reinterpret_cast<const long long*>(tgv)[warp];
        else      t = reinterpret_cast<const int*>(tgv)[warp];

        red_add_v4(&g_P[t * D + lane * 4], a.x * invp, a.y * invp, a.z * invp, a.w * invp);
        red_add_v4(&g_Z[t * D + lane * 4], b.x * invz, b.y * invz, b.z * invz, b.w * invz);

        if (lane == 0) {
            atomicAdd(&g_cnt[t], 1);
            diag = (double)(dp * invp * invz);
        }
    }
    if (lane == 0) sdp[warp_in_blk] = diag;
    __syncthreads();
    if (threadIdx.x == 0) {
        double s = sdp[0] + sdp[1] + sdp[2] + sdp[3]
                 + sdp[4] + sdp[5] + sdp[6] + sdp[7];
        atomicAdd(&g_Ddiag, s);
    }
}

// ---------------------------------------------------------------------------
// Fused: per-class dot (warp per class) + pair count + scratch re-zero +
// last-block epilogue. grid = NCLASS/8 blocks of 256 threads.
__global__ void final_kernel(float* __restrict__ out, int n_blocks) {
    int lane = threadIdx.x & 31;
    int wid  = threadIdx.x >> 5;                 // 0..7
    int c    = blockIdx.x * 8 + wid;             // class handled by this warp
    int idx  = c * (D / 4) + lane;               // float4 index into g_P/g_Z

    float4 p = reinterpret_cast<const float4*>(g_P)[idx];
    float4 z = reinterpret_cast<const float4*>(g_Z)[idx];
    float dot = p.x * z.x + p.y * z.y + p.z * z.z + p.w * z.w;
    #pragma unroll
    for (int o = 16; o > 0; o >>= 1)
        dot += __shfl_xor_sync(0xFFFFFFFFu, dot, o);

    if (lane == 0) {
        atomicAdd(&g_S, (double)dot);
        unsigned long long m = (unsigned long long)g_cnt[c];
        if (m > 1ull) atomicAdd(&g_pairs, m * (m - 1ull) / 2ull);
    }

    // Re-zero the slices this block owns (restores launch-entry invariant).
    float4 zero4 = make_float4(0.f, 0.f, 0.f, 0.f);
    reinterpret_cast<float4*>(g_P)[idx] = zero4;
    reinterpret_cast<float4*>(g_Z)[idx] = zero4;
    if (lane == 0) g_cnt[c] = 0;

    __syncthreads();
    __threadfence();
    if (threadIdx.x == 0) {
        unsigned int done = atomicAdd(&g_done, 1u);
        if (done == (unsigned int)(n_blocks - 1)) {
            // last block: epilogue + scalar reset
            double np = (g_pairs > 0ull) ? (double)g_pairs : 1.0;
            out[0] = (float)(-0.5 * (g_S - g_Ddiag) / np);
            g_S = 0.0; g_Ddiag = 0.0; g_pairs = 0ull;
            g_done = 0u;
        }
    }
}

// ---------------------------------------------------------------------------
extern "C" void kernel_launch(void* const* d_in, const int* in_sizes, int n_in,
                              void* d_out, int out_size) {
    const float* ps  = (const float*)d_in[0];
    const float* zs  = (const float*)d_in[1];
    const void*  tgt = d_in[2];
    float*       out = (float*)d_out;

    int n_rows = in_sizes[0] / D;   // 8192

    accum_kernel<<<(n_rows + 7) / 8, 256>>>(ps, zs, tgt, n_rows);
    int fb = NCLASS / 8;            // 64 blocks
    final_kernel<<<fb, 256>>>(out, fb);
}